// round 16
// baseline (speedup 1.0000x reference)
#include <cuda_runtime.h>
#include <cstdint>

// LinearInterpolator on GB300 — parallel probe-count correction.
//  Upper-bound LUT: lut[j] = clamp(max{i : cell(x_i) <= j}, 0, n-2). Because
//  knots are sorted, idx_true = lut - (# of consecutive-from-top probes > x).
//  Hot path: LDS.16 lut -> FOUR PARALLEL LDS.32 probes x[lut-3..lut] ->
//  steps = sum of monotone predicates, idx = lut - steps, x[idx] selected
//  from probes via SELs (no reload) -> LDS.64 (y,slope) -> FMA.
//  steps==4 (P ~ 0.3%/lane) falls to a scalar loop. No warp votes, no serial
//  LDS chains, no divergence in the common path.
//  s_x front-padded with 4 x -INF so probes at lut-3 >= -3 are in-bounds.

#define LUT_SIZE 16384
#define THREADS  1024

__device__ unsigned short g_lut[LUT_SIZE + 2];

__device__ __forceinline__ int cell_of(float v, float inv_w, float c0) {
    // Identical instruction sequence in build + main kernels (monotone in v).
    return (int)fmaf(v, inv_w, c0);
}

// lut[j] = last knot index with cell(x_i) <= j, clamped to [0, n-2].
__global__ void build_lut_kernel(const float* __restrict__ xp, int n) {
    int j = blockIdx.x * blockDim.x + threadIdx.x;
    if (j > LUT_SIZE + 1) return;
    float x_lo = __ldg(&xp[0]);
    float x_hi = __ldg(&xp[n - 1]);
    float inv_w = __fdiv_rn((float)LUT_SIZE, __fsub_rn(x_hi, x_lo));
    float c0 = __fmul_rn(-x_lo, inv_w);
    int lo = 0, hi = n;
    #pragma unroll 1
    while (lo < hi) {
        int mid = (lo + hi) >> 1;
        if (cell_of(__ldg(&xp[mid]), inv_w, c0) <= j) lo = mid + 1;
        else hi = mid;
    }
    int ub = lo - 1;                 // >= 0 since cell(x_points[0]) = 0 <= j
    if (ub < 0) ub = 0;
    if (ub > n - 2) ub = n - 2;
    g_lut[j] = (unsigned short)ub;
}

extern __shared__ unsigned char smem_raw[];

__device__ __forceinline__ float interp1(float x,
                                         const float* __restrict__ s_x,
                                         const float2* __restrict__ s_ys,
                                         const unsigned short* __restrict__ s_lut,
                                         float inv_w, float c0) {
    int j = cell_of(x, inv_w, c0);          // j <= LUT_SIZE-1 (x < x[n-2] < x_hi)
    int lut = (int)s_lut[j];
    // Four independent probes (monotone: q0 >= q1 >= q2 >= q3).
    float q0 = s_x[lut];
    float q1 = s_x[lut - 1];
    float q2 = s_x[lut - 2];
    float q3 = s_x[lut - 3];
    bool p0 = q0 > x, p1 = q1 > x, p2 = q2 > x, p3 = q3 > x;
    // Predicates are leading-true (sorted), so their sum is the step count.
    int steps = (int)p0 + (int)p1 + (int)p2 + (int)p3;
    int idx = lut - steps;
    float xv = p0 ? (p1 ? (p2 ? q3 : q2) : q1) : q0;   // x[idx] from probes
    if (p3) {                                // steps == 4: rare (~0.3%/lane)
        float xw = s_x[idx];                 // probe x[lut-4]
        while (xw > x) { xw = s_x[--idx]; }  // loop stops by x >= x[0]
        xv = xw;
    }
    float2 ys = s_ys[idx];                   // (y_i, slope_i)
    return fmaf(ys.y, __fsub_rn(x, xv), ys.x);
}

__global__ __launch_bounds__(THREADS, 1)
void interp_kernel(const float* __restrict__ xs, const float* __restrict__ xp,
                   const float* __restrict__ yp, float* __restrict__ out,
                   int total, int n) {
    float* s_base = reinterpret_cast<float*>(smem_raw);
    float* s_x = s_base + 4;                                   // front pad of 4
    float2* s_ys = reinterpret_cast<float2*>(smem_raw + (size_t)(n + 4) * 4);
    unsigned short* s_lut =
        reinterpret_cast<unsigned short*>(smem_raw + (size_t)(n + 4) * 4
                                                   + (size_t)n * 8);

    if (threadIdx.x < 4)
        s_base[threadIdx.x] = __int_as_float(0xFF800000);      // -INF pad
    // Stage knots (slope precomputed) and LUT into SMEM.
    for (int i = threadIdx.x; i < n; i += blockDim.x) {
        float xi = __ldg(&xp[i]);
        float yi = __ldg(&yp[i]);
        s_x[i] = xi;
        float sl = 0.0f;
        if (i < n - 1)
            sl = __fdiv_rn(__ldg(&yp[i + 1]) - yi, __ldg(&xp[i + 1]) - xi);
        s_ys[i] = make_float2(yi, sl);
    }
    for (int i = threadIdx.x; i < LUT_SIZE + 2; i += blockDim.x)
        s_lut[i] = g_lut[i];
    __syncthreads();

    float x_lo = s_x[0];
    float x_hi = s_x[n - 1];
    float inv_w = __fdiv_rn((float)LUT_SIZE, __fsub_rn(x_hi, x_lo));
    float c0 = __fmul_rn(-x_lo, inv_w);

    int tid = blockIdx.x * blockDim.x + threadIdx.x;
    int stride = gridDim.x * blockDim.x;
    int T4 = total >> 2;

    const float4* __restrict__ xs4 = reinterpret_cast<const float4*>(xs);
    float4* __restrict__ out4 = reinterpret_cast<float4*>(out);

    // ILP = 8: two float4 per iteration; all probe levels are branch-free so
    // the 8 chains' LDS batches pipeline through the crossbar.
    for (int t = tid; t < T4; t += 2 * stride) {
        int t2 = t + stride;
        bool hb = t2 < T4;
        float4 a = xs4[t];
        float4 b = hb ? xs4[t2] : a;

        float v[8] = {a.x, a.y, a.z, a.w, b.x, b.y, b.z, b.w};
        float r[8];
        #pragma unroll
        for (int k = 0; k < 8; k++)
            r[k] = interp1(v[k], s_x, s_ys, s_lut, inv_w, c0);

        out4[t] = make_float4(r[0], r[1], r[2], r[3]);
        if (hb) out4[t2] = make_float4(r[4], r[5], r[6], r[7]);
    }
    for (int t = (T4 << 2) + tid; t < total; t += stride)
        out[t] = interp1(xs[t], s_x, s_ys, s_lut, inv_w, c0);
}

extern "C" void kernel_launch(void* const* d_in, const int* in_sizes, int n_in,
                              void* d_out, int out_size) {
    const float* xs = (const float*)d_in[0];
    const float* xp = (const float*)d_in[1];
    const float* yp = (const float*)d_in[2];
    float* out = (float*)d_out;
    int total = in_sizes[0];
    int n = in_sizes[1];

    build_lut_kernel<<<(LUT_SIZE + 2 + 255) / 256, 256>>>(xp, n);

    size_t smem_bytes = (size_t)(n + 4) * 4 + (size_t)n * 8
                      + (size_t)(LUT_SIZE + 2) * 2;
    cudaFuncSetAttribute(interp_kernel,
                         cudaFuncAttributeMaxDynamicSharedMemorySize,
                         (int)smem_bytes);

    int sm_count = 148, dev = 0;
    cudaGetDevice(&dev);
    cudaDeviceGetAttribute(&sm_count, cudaDevAttrMultiProcessorCount, dev);
    if (sm_count <= 0) sm_count = 148;

    interp_kernel<<<sm_count, THREADS, smem_bytes>>>(xs, xp, yp, out, total, n);
}